// round 1
// baseline (speedup 1.0000x reference)
#include <cuda_runtime.h>
#include <math.h>

// Problem constants
#define T_DIM 256
#define S_DIM 2048
#define C_DIM 128
#define HID   32
#define G3    192   // 3 * L
#define L_DIM 64

// Scratch for gx = h_proj @ W_ih^T + b_ih, layout [t][j][s] (j in 0..191)
// 256*192*2048 floats = 402 MB
__device__ float g_gx[(size_t)T_DIM * G3 * S_DIM];

// ---------------------------------------------------------------------------
// Phase 1: fused MLP (C->32->64, LeakyReLU) + gx projection (64->192)
// One thread per (t,s) row. Weights in shared (broadcast reads).
// h1/h2 staged in shared [k][tid] to allow runtime-k indexing without spills.
// ---------------------------------------------------------------------------
__global__ void __launch_bounds__(256) mlp_gx_kernel(
    const float* __restrict__ x,
    const float* __restrict__ W1, const float* __restrict__ b1,
    const float* __restrict__ W2, const float* __restrict__ b2,
    const float* __restrict__ Wih, const float* __restrict__ bih)
{
    extern __shared__ float sm[];
    float* W1s  = sm;                  // 128*32 = 4096
    float* b1s  = W1s  + 4096;         // 32
    float* W2s  = b1s  + 32;           // 32*64 = 2048
    float* b2s  = W2s  + 2048;         // 64
    float* WihT = b2s  + 64;           // 64 rows * stride 196 = 12544  (WihT[k][j])
    float* bihs = WihT + 12544;        // 192
    float* h1s  = bihs + 192;          // 32*256 = 8192   [k][tid]
    float* h2s  = h1s  + 8192;         // 64*256 = 16384  [k][tid]
    // total = 43552 floats = 174208 bytes

    const int tid = threadIdx.x;

    // Cooperative weight staging
    for (int i = tid; i < 4096; i += 256) W1s[i] = W1[i];
    for (int i = tid; i < 2048; i += 256) W2s[i] = W2[i];
    for (int i = tid; i < 12288; i += 256) {
        int j = i >> 6, k = i & 63;            // Wih is (192,64) row-major
        WihT[k * 196 + j] = Wih[i];
    }
    if (tid < 32)  b1s[tid] = b1[tid];
    if (tid < 64)  b2s[tid] = b2[tid];
    if (tid < 192) bihs[tid] = bih[tid];
    __syncthreads();

    const int row = blockIdx.x * 256 + tid;    // 2048 blocks * 256 = T*S
    const int t = row >> 11;                   // row / 2048
    const int s = row & 2047;

    // ---- GEMM1: h1 = lrelu(x @ W1 + b1), K=128, N=32 ----
    float acc1[32];
    #pragma unroll
    for (int c = 0; c < 32; c++) acc1[c] = b1s[c];

    const float4* xv = reinterpret_cast<const float4*>(x + (size_t)row * C_DIM);
    #pragma unroll 4
    for (int k4 = 0; k4 < 32; k4++) {
        float4 xq = __ldg(&xv[k4]);
        float xr[4] = {xq.x, xq.y, xq.z, xq.w};
        #pragma unroll
        for (int kk = 0; kk < 4; kk++) {
            const float4* w = reinterpret_cast<const float4*>(&W1s[(k4 * 4 + kk) * 32]);
            float xk = xr[kk];
            #pragma unroll
            for (int c4 = 0; c4 < 8; c4++) {
                float4 wv = w[c4];
                acc1[c4*4+0] += xk * wv.x;
                acc1[c4*4+1] += xk * wv.y;
                acc1[c4*4+2] += xk * wv.z;
                acc1[c4*4+3] += xk * wv.w;
            }
        }
    }
    #pragma unroll
    for (int c = 0; c < 32; c++) {
        float v = acc1[c];
        h1s[c * 256 + tid] = fmaxf(v, 0.01f * v);   // LeakyReLU
    }

    // ---- GEMM2: h2 = lrelu(h1 @ W2 + b2), K=32, N=64 ----
    float acc2[64];
    #pragma unroll
    for (int c = 0; c < 64; c++) acc2[c] = b2s[c];

    #pragma unroll 2
    for (int k = 0; k < 32; k++) {
        float hv = h1s[k * 256 + tid];
        const float4* w = reinterpret_cast<const float4*>(&W2s[k * 64]);
        #pragma unroll
        for (int c4 = 0; c4 < 16; c4++) {
            float4 wv = w[c4];
            acc2[c4*4+0] += hv * wv.x;
            acc2[c4*4+1] += hv * wv.y;
            acc2[c4*4+2] += hv * wv.z;
            acc2[c4*4+3] += hv * wv.w;
        }
    }
    #pragma unroll
    for (int c = 0; c < 64; c++) {
        float v = acc2[c];
        h2s[c * 256 + tid] = fmaxf(v, 0.01f * v);
    }

    // ---- GEMM3: gx = h2 @ W_ih^T + b_ih, K=64, N=192 (3 chunks of 64) ----
    for (int ch = 0; ch < 3; ch++) {
        const int j0 = ch * 64;
        float acc[64];
        #pragma unroll
        for (int j = 0; j < 64; j++) acc[j] = bihs[j0 + j];

        #pragma unroll 2
        for (int k = 0; k < 64; k++) {
            float hv = h2s[k * 256 + tid];
            const float4* w = reinterpret_cast<const float4*>(&WihT[k * 196 + j0]);
            #pragma unroll
            for (int c4 = 0; c4 < 16; c4++) {
                float4 wv = w[c4];
                acc[c4*4+0] += hv * wv.x;
                acc[c4*4+1] += hv * wv.y;
                acc[c4*4+2] += hv * wv.z;
                acc[c4*4+3] += hv * wv.w;
            }
        }
        // Store to gx[t][j0+j][s] — lanes consecutive in s -> coalesced
        float* gdst = &g_gx[((size_t)t * G3 + j0) * S_DIM + s];
        #pragma unroll
        for (int j = 0; j < 64; j++) gdst[(size_t)j * S_DIM] = acc[j];
    }
}

// ---------------------------------------------------------------------------
// Phase 2: GRU over T=256 steps. Each block owns 16 stocks; recurrence is
// per-stock independent so blocks loop over t locally (no grid sync).
// Thread (sq = tid/64, jj = tid%64) computes gh for 4 stocks x 3 gates at
// hidden column jj. h lives in shared; gx prefetched into regs to hide HBM.
// ---------------------------------------------------------------------------
__global__ void __launch_bounds__(256) gru_kernel(
    const float* __restrict__ Whh, const float* __restrict__ bhh,
    float* __restrict__ out)
{
    extern __shared__ float sm[];
    float* WhhT = sm;              // 64 * 196 = 12544   (WhhT[k][j])
    float* bhhs = WhhT + 12544;    // 192
    float* h_s  = bhhs + 192;      // 16 * 64 = 1024     (h_s[s][k])
    float* gx_s = h_s + 1024;      // 192 * 17 = 3264    (gx_s[j][s], pad 17)
    // total = 17024 floats = 68096 bytes

    const int tid = threadIdx.x;
    const int jj  = tid & 63;      // hidden column (constant stride across warp)
    const int sq  = tid >> 6;      // stock quad (constant within a warp)
    const int s0  = blockIdx.x * 16;

    for (int i = tid; i < 12288; i += 256) {
        int j = i >> 6, k = i & 63;        // Whh is (192,64) row-major
        WhhT[k * 196 + j] = Whh[i];
    }
    if (tid < 192) bhhs[tid] = bhh[tid];
    for (int i = tid; i < 1024; i += 256) h_s[i] = 0.0f;
    __syncthreads();

    for (int t = 0; t < T_DIM; t++) {
        // Prefetch gx tile for this step into registers (hides DRAM latency
        // behind the GEMM below). 192*16 floats / 256 threads = 12 each.
        float gbuf[12];
        #pragma unroll
        for (int i = 0; i < 12; i++) {
            int idx = tid + 256 * i;
            int j = idx >> 4, ss = idx & 15;
            gbuf[i] = g_gx[((size_t)t * G3 + j) * S_DIM + s0 + ss];
        }

        // gh = h @ W_hh^T + b_hh for 4 stocks x 3 gates at column jj
        float acc[12];
        #pragma unroll
        for (int si = 0; si < 4; si++)
            #pragma unroll
            for (int g = 0; g < 3; g++)
                acc[si * 3 + g] = bhhs[g * 64 + jj];

        #pragma unroll 4
        for (int k4 = 0; k4 < 16; k4++) {
            float4 h0 = *reinterpret_cast<const float4*>(&h_s[(sq*4+0)*64 + k4*4]);
            float4 h1 = *reinterpret_cast<const float4*>(&h_s[(sq*4+1)*64 + k4*4]);
            float4 h2 = *reinterpret_cast<const float4*>(&h_s[(sq*4+2)*64 + k4*4]);
            float4 h3 = *reinterpret_cast<const float4*>(&h_s[(sq*4+3)*64 + k4*4]);
            float ha[4][4] = {{h0.x,h0.y,h0.z,h0.w},{h1.x,h1.y,h1.z,h1.w},
                              {h2.x,h2.y,h2.z,h2.w},{h3.x,h3.y,h3.z,h3.w}};
            #pragma unroll
            for (int kk = 0; kk < 4; kk++) {
                int k = k4 * 4 + kk;
                float w0 = WhhT[k * 196 + jj];
                float w1 = WhhT[k * 196 + 64 + jj];
                float w2 = WhhT[k * 196 + 128 + jj];
                #pragma unroll
                for (int si = 0; si < 4; si++) {
                    float hv = ha[si][kk];
                    acc[si*3+0] += hv * w0;
                    acc[si*3+1] += hv * w1;
                    acc[si*3+2] += hv * w2;
                }
            }
        }

        // Stage gx into shared (conflict-free via stride 17)
        #pragma unroll
        for (int i = 0; i < 12; i++) {
            int idx = tid + 256 * i;
            int j = idx >> 4, ss = idx & 15;
            gx_s[j * 17 + ss] = gbuf[i];
        }
        __syncthreads();   // gx visible; all GEMM reads of h_s complete

        // Gates. Each thread reads/writes only its own (s, jj) h elements,
        // so no extra barrier needed between read-old-h and write-new-h.
        float hnew[4];
        #pragma unroll
        for (int si = 0; si < 4; si++) {
            int s = sq * 4 + si;
            float gr = gx_s[jj * 17 + s];
            float gz = gx_s[(64 + jj) * 17 + s];
            float gn = gx_s[(128 + jj) * 17 + s];
            float r = 1.0f / (1.0f + __expf(-(gr + acc[si*3+0])));
            float z = 1.0f / (1.0f + __expf(-(gz + acc[si*3+1])));
            float narg = gn + r * acc[si*3+2];
            float e = __expf(-2.0f * fabsf(narg));          // overflow-safe tanh
            float n = (1.0f - e) / (1.0f + e);
            n = copysignf(n, narg);
            float ho = h_s[s * 64 + jj];
            hnew[si] = (1.0f - z) * n + z * ho;
        }
        #pragma unroll
        for (int si = 0; si < 4; si++)
            h_s[(sq * 4 + si) * 64 + jj] = hnew[si];
        __syncthreads();   // h_t visible before next step's GEMM
    }

    // Write final hidden state: out[(s0+s)*64 + jj], coalesced over jj
    #pragma unroll
    for (int si = 0; si < 4; si++)
        out[(size_t)(s0 + sq * 4 + si) * L_DIM + jj] = h_s[(sq * 4 + si) * 64 + jj];
}

// ---------------------------------------------------------------------------
extern "C" void kernel_launch(void* const* d_in, const int* in_sizes, int n_in,
                              void* d_out, int out_size)
{
    const float* x   = (const float*)d_in[0];
    const float* W1  = (const float*)d_in[1];
    const float* b1  = (const float*)d_in[2];
    const float* W2  = (const float*)d_in[3];
    const float* b2  = (const float*)d_in[4];
    const float* Wih = (const float*)d_in[5];
    const float* Whh = (const float*)d_in[6];
    const float* bih = (const float*)d_in[7];
    const float* bhh = (const float*)d_in[8];
    float* out = (float*)d_out;

    static bool attrs_set = false;
    if (!attrs_set) {
        cudaFuncSetAttribute(mlp_gx_kernel,
                             cudaFuncAttributeMaxDynamicSharedMemorySize, 43552 * 4);
        cudaFuncSetAttribute(gru_kernel,
                             cudaFuncAttributeMaxDynamicSharedMemorySize, 17024 * 4);
        attrs_set = true;
    }

    // Phase 1: 2048 blocks * 256 threads = one thread per (t,s) row
    mlp_gx_kernel<<<2048, 256, 43552 * 4>>>(x, W1, b1, W2, b2, Wih, bih);
    // Phase 2: 128 blocks * 16 stocks, sequential over T inside the kernel
    gru_kernel<<<128, 256, 17024 * 4>>>(Whh, bhh, out);
}